// round 3
// baseline (speedup 1.0000x reference)
#include <cuda_runtime.h>
#include <stdint.h>

#define IN_F   256
#define OUT_F  64
#define MAX_NODES 100000

// Scratch ping-pong buffers (device globals: allocation-free scratch)
__device__ float g_buf0[(size_t)MAX_NODES * OUT_F];
__device__ float g_buf1[(size_t)MAX_NODES * OUT_F];

// ---------------------------------------------------------------------------
// GEMM: y[n,f] = sum_k x[n,k] * W[f,k] + b[f]
// Tile: 64 nodes x 64 feats x 32 k, 256 threads, 4x4 micro-tile per thread.
// ---------------------------------------------------------------------------
#define TM 64
#define TK 32

__global__ __launch_bounds__(256) void sgc_gemm_kernel(
    const float* __restrict__ x, const float* __restrict__ W,
    const float* __restrict__ b, float* __restrict__ y, int n_nodes)
{
    __shared__ float As[TM][TK + 1];     // node-major, +1 pad: bank = (node+k)%32
    __shared__ float Bs[OUT_F][TK + 1];  // feat-major

    const int t  = threadIdx.x;
    const int tx = t & 15;        // 16 feat groups
    const int ty = t >> 4;        // 16 node groups
    const int node_base = blockIdx.x * TM;

    float acc[4][4] = {};

    for (int k0 = 0; k0 < IN_F; k0 += TK) {
        // Load As: 64 nodes x 32 k = 512 float4, 2 per thread.
        // Mapping: 8 consecutive threads load one row's 32-float chunk (coalesced 128B).
        #pragma unroll
        for (int r = 0; r < 2; r++) {
            int idx  = t + r * 256;       // 0..511
            int node = idx >> 3;
            int kq   = idx & 7;
            int gn   = node_base + node;
            float4 v = make_float4(0.f, 0.f, 0.f, 0.f);
            if (gn < n_nodes)
                v = *reinterpret_cast<const float4*>(x + (size_t)gn * IN_F + k0 + kq * 4);
            As[node][kq * 4 + 0] = v.x;
            As[node][kq * 4 + 1] = v.y;
            As[node][kq * 4 + 2] = v.z;
            As[node][kq * 4 + 3] = v.w;
        }
        // Load Bs: 64 feats x 32 k = 512 float4, 2 per thread.
        #pragma unroll
        for (int r = 0; r < 2; r++) {
            int idx = t + r * 256;
            int f   = idx >> 3;
            int kq  = idx & 7;
            float4 v = *reinterpret_cast<const float4*>(W + (size_t)f * IN_F + k0 + kq * 4);
            Bs[f][kq * 4 + 0] = v.x;
            Bs[f][kq * 4 + 1] = v.y;
            Bs[f][kq * 4 + 2] = v.z;
            Bs[f][kq * 4 + 3] = v.w;
        }
        __syncthreads();

        #pragma unroll
        for (int k = 0; k < TK; k++) {
            float a[4], bb[4];
            #pragma unroll
            for (int i = 0; i < 4; i++) a[i]  = As[ty * 4 + i][k];
            #pragma unroll
            for (int j = 0; j < 4; j++) bb[j] = Bs[tx * 4 + j][k];
            #pragma unroll
            for (int i = 0; i < 4; i++)
                #pragma unroll
                for (int j = 0; j < 4; j++)
                    acc[i][j] += a[i] * bb[j];
        }
        __syncthreads();
    }

    // Epilogue: add bias, store float4 per (node, 4 feats)
    float4 bias = *reinterpret_cast<const float4*>(b + tx * 4);
    #pragma unroll
    for (int i = 0; i < 4; i++) {
        int gn = node_base + ty * 4 + i;
        if (gn < n_nodes) {
            float4 o;
            o.x = acc[i][0] + bias.x;
            o.y = acc[i][1] + bias.y;
            o.z = acc[i][2] + bias.z;
            o.w = acc[i][3] + bias.w;
            *reinterpret_cast<float4*>(y + (size_t)gn * OUT_F + tx * 4) = o;
        }
    }
}

// ---------------------------------------------------------------------------
// Zero a float buffer (float4 stores)
// ---------------------------------------------------------------------------
__global__ void sgc_zero_kernel(float4* __restrict__ p, int n4)
{
    int i = blockIdx.x * blockDim.x + threadIdx.x;
    if (i < n4) p[i] = make_float4(0.f, 0.f, 0.f, 0.f);
}

// ---------------------------------------------------------------------------
// SPMM scatter hop: B[dst] += w * A[src].  16 threads per edge, one float4
// per thread, reduced with red.global.add.v4.f32 (sm_90+ vector red).
// ---------------------------------------------------------------------------
__global__ __launch_bounds__(256) void sgc_scatter_kernel(
    const float* __restrict__ A, float* __restrict__ B,
    const int* __restrict__ src, const int* __restrict__ dst,
    const float* __restrict__ wt, int n_edges)
{
    int idx  = blockIdx.x * blockDim.x + threadIdx.x;
    int e    = idx >> 4;
    int lane = idx & 15;
    if (e >= n_edges) return;

    int   s  = __ldg(src + e);
    int   d  = __ldg(dst + e);
    float we = __ldg(wt  + e);

    float4 v = __ldg(reinterpret_cast<const float4*>(A) + (size_t)s * 16 + lane);
    v.x *= we; v.y *= we; v.z *= we; v.w *= we;

    float* bp = B + (size_t)d * OUT_F + lane * 4;
    asm volatile("red.global.add.v4.f32 [%0], {%1, %2, %3, %4};"
                 :: "l"(bp), "f"(v.x), "f"(v.y), "f"(v.z), "f"(v.w)
                 : "memory");
}

// ---------------------------------------------------------------------------
// Launch
// ---------------------------------------------------------------------------
extern "C" void kernel_launch(void* const* d_in, const int* in_sizes, int n_in,
                              void* d_out, int out_size)
{
    const float* x   = (const float*)d_in[0];
    const float* W   = (const float*)d_in[1];
    const float* b   = (const float*)d_in[2];
    const int*   src = (const int*)  d_in[3];
    const int*   dst = (const int*)  d_in[4];
    const float* wt  = (const float*)d_in[5];

    const int N = in_sizes[0] / IN_F;
    const int E = in_sizes[3];
    float* out  = (float*)d_out;

    float *buf0 = nullptr, *buf1 = nullptr;
    cudaGetSymbolAddress((void**)&buf0, g_buf0);
    cudaGetSymbolAddress((void**)&buf1, g_buf1);

    const int n4        = (N * OUT_F) / 4;
    const int zeroBlks  = (n4 + 255) / 256;
    const int gemmBlks  = (N + TM - 1) / TM;
    const int scatThrds = E * 16;
    const int scatBlks  = (scatThrds + 255) / 256;

    // 1) Projection: buf0 = x @ W.T + b
    sgc_gemm_kernel<<<gemmBlks, 256>>>(x, W, b, buf0, N);

    // 2) Hop 1: buf1 = Adj * buf0
    sgc_zero_kernel<<<zeroBlks, 256>>>((float4*)buf1, n4);
    sgc_scatter_kernel<<<scatBlks, 256>>>(buf0, buf1, src, dst, wt, E);

    // 3) Hop 2: buf0 = Adj * buf1
    sgc_zero_kernel<<<zeroBlks, 256>>>((float4*)buf0, n4);
    sgc_scatter_kernel<<<scatBlks, 256>>>(buf1, buf0, src, dst, wt, E);

    // 4) Hop 3: out = Adj * buf0
    sgc_zero_kernel<<<zeroBlks, 256>>>((float4*)out, n4);
    sgc_scatter_kernel<<<scatBlks, 256>>>(buf0, out, src, dst, wt, E);
}

// round 4
// speedup vs baseline: 1.5324x; 1.5324x over previous
#include <cuda_runtime.h>
#include <stdint.h>

#define IN_F   256
#define OUT_F  64
#define MAX_NODES 100000
#define MAX_EDGES 1600000

// ---------------------------------------------------------------------------
// Device-global scratch (allocation-free)
// ---------------------------------------------------------------------------
__device__ float g_buf0[(size_t)MAX_NODES * OUT_F];
__device__ float g_buf1[(size_t)MAX_NODES * OUT_F];
__device__ int   g_deg[MAX_NODES];
__device__ int   g_off[MAX_NODES];
__device__ int   g_cursor[MAX_NODES];
__device__ int   g_bsum[256];
__device__ int2  g_csr[MAX_EDGES];   // (src, weight bits), grouped by dst

// ---------------------------------------------------------------------------
// f32x2 packed-FMA helpers (Blackwell: only reachable via PTX)
// ---------------------------------------------------------------------------
__device__ __forceinline__ unsigned long long pack2(float lo, float hi) {
    unsigned long long r;
    asm("mov.b64 %0, {%1,%2};" : "=l"(r) : "f"(lo), "f"(hi));
    return r;
}
__device__ __forceinline__ void unpack2(unsigned long long v, float& lo, float& hi) {
    asm("mov.b64 {%0,%1}, %2;" : "=f"(lo), "=f"(hi) : "l"(v));
}
__device__ __forceinline__ unsigned long long fma2(unsigned long long a,
                                                   unsigned long long b,
                                                   unsigned long long c) {
    unsigned long long d;
    asm("fma.rn.f32x2 %0, %1, %2, %3;" : "=l"(d) : "l"(a), "l"(b), "l"(c));
    return d;
}

// ---------------------------------------------------------------------------
// GEMM: y[n,f] = sum_k x[n,k]*W[f,k] + b[f]
// 64-node x 64-feat x 32-k tiles; thread = 4 nodes x 4 feats (strided by 16);
// k-pair packed FFMA2, horizontal add at the end.
// ---------------------------------------------------------------------------
#define TM 64
#define TK 32
#define LD 34   // leading dim: 17 (odd) 8B-units -> conflict-free LDS.64

__global__ __launch_bounds__(256, 2) void sgc_gemm_kernel(
    const float* __restrict__ x, const float* __restrict__ W,
    const float* __restrict__ bias, float* __restrict__ y, int n_nodes)
{
    __shared__ float As[TM][LD];
    __shared__ float Bs[OUT_F][LD];

    const int t  = threadIdx.x;
    const int tx = t & 15;     // feats: tx, tx+16, tx+32, tx+48
    const int ty = t >> 4;     // nodes: ty, ty+16, ty+32, ty+48
    const int node_base = blockIdx.x * TM;

    unsigned long long acc[4][4];
    #pragma unroll
    for (int j = 0; j < 4; j++) {
        unsigned long long binit = pack2(bias[tx + 16 * j], 0.0f);
        #pragma unroll
        for (int i = 0; i < 4; i++) acc[i][j] = binit;
    }

    for (int k0 = 0; k0 < IN_F; k0 += TK) {
        // Load As: 64 rows x 32 k. idx>>3 = row, idx&7 = k-quad. Coalesced 128B.
        #pragma unroll
        for (int r = 0; r < 2; r++) {
            int idx = t + r * 256;
            int row = idx >> 3;
            int kq  = idx & 7;
            int gn  = node_base + row;
            float4 v = make_float4(0.f, 0.f, 0.f, 0.f);
            if (gn < n_nodes)
                v = *reinterpret_cast<const float4*>(x + (size_t)gn * IN_F + k0 + kq * 4);
            float2* p = reinterpret_cast<float2*>(&As[row][kq * 4]);
            p[0] = make_float2(v.x, v.y);
            p[1] = make_float2(v.z, v.w);
        }
        // Load Bs: 64 feat rows x 32 k.
        #pragma unroll
        for (int r = 0; r < 2; r++) {
            int idx = t + r * 256;
            int f   = idx >> 3;
            int kq  = idx & 7;
            float4 v = *reinterpret_cast<const float4*>(W + (size_t)f * IN_F + k0 + kq * 4);
            float2* p = reinterpret_cast<float2*>(&Bs[f][kq * 4]);
            p[0] = make_float2(v.x, v.y);
            p[1] = make_float2(v.z, v.w);
        }
        __syncthreads();

        #pragma unroll
        for (int k = 0; k < TK; k += 2) {
            unsigned long long a2[4], b2[4];
            #pragma unroll
            for (int i = 0; i < 4; i++)
                a2[i] = *reinterpret_cast<const unsigned long long*>(&As[ty + 16 * i][k]);
            #pragma unroll
            for (int j = 0; j < 4; j++)
                b2[j] = *reinterpret_cast<const unsigned long long*>(&Bs[tx + 16 * j][k]);
            #pragma unroll
            for (int i = 0; i < 4; i++)
                #pragma unroll
                for (int j = 0; j < 4; j++)
                    acc[i][j] = fma2(a2[i], b2[j], acc[i][j]);
        }
        __syncthreads();
    }

    #pragma unroll
    for (int i = 0; i < 4; i++) {
        int gn = node_base + ty + 16 * i;
        if (gn < n_nodes) {
            #pragma unroll
            for (int j = 0; j < 4; j++) {
                float lo, hi;
                unpack2(acc[i][j], lo, hi);
                y[(size_t)gn * OUT_F + tx + 16 * j] = lo + hi;
            }
        }
    }
}

// ---------------------------------------------------------------------------
// CSR build: zero -> histogram -> scan(A,B,C) -> reorder
// ---------------------------------------------------------------------------
__global__ void sgc_zero_deg(int* __restrict__ deg, int n)
{
    int i = blockIdx.x * blockDim.x + threadIdx.x;
    if (i < n) deg[i] = 0;
}

__global__ void sgc_hist(const int* __restrict__ dst, int* __restrict__ deg, int E)
{
    int i = blockIdx.x * blockDim.x + threadIdx.x;
    if (i < E) atomicAdd(&deg[dst[i]], 1);   // no return use -> REDG
}

__global__ void sgc_scanA(const int* __restrict__ deg, int* __restrict__ off,
                          int* __restrict__ bsum, int n)
{
    __shared__ int s[256];
    int t = threadIdx.x;
    int base = blockIdx.x * 1024 + t * 4;
    int v0 = (base + 0 < n) ? deg[base + 0] : 0;
    int v1 = (base + 1 < n) ? deg[base + 1] : 0;
    int v2 = (base + 2 < n) ? deg[base + 2] : 0;
    int v3 = (base + 3 < n) ? deg[base + 3] : 0;
    int tsum = v0 + v1 + v2 + v3;
    s[t] = tsum;
    __syncthreads();
    for (int o = 1; o < 256; o <<= 1) {
        int xv = (t >= o) ? s[t - o] : 0;
        __syncthreads();
        s[t] += xv;
        __syncthreads();
    }
    int excl = s[t] - tsum;
    if (t == 255) bsum[blockIdx.x] = s[255];
    if (base + 0 < n) off[base + 0] = excl;
    if (base + 1 < n) off[base + 1] = excl + v0;
    if (base + 2 < n) off[base + 2] = excl + v0 + v1;
    if (base + 3 < n) off[base + 3] = excl + v0 + v1 + v2;
}

__global__ void sgc_scanB(int* __restrict__ bsum, int nb)
{
    __shared__ int s[256];
    int t = threadIdx.x;
    int v = (t < nb) ? bsum[t] : 0;
    s[t] = v;
    __syncthreads();
    for (int o = 1; o < 256; o <<= 1) {
        int xv = (t >= o) ? s[t - o] : 0;
        __syncthreads();
        s[t] += xv;
        __syncthreads();
    }
    if (t < nb) bsum[t] = s[t] - v;   // exclusive
}

__global__ void sgc_scanC(int* __restrict__ off, int* __restrict__ cursor,
                          const int* __restrict__ bsum, int n)
{
    int i = blockIdx.x * blockDim.x + threadIdx.x;
    if (i < n) {
        int v = off[i] + bsum[i >> 10];
        off[i] = v;
        cursor[i] = v;
    }
}

__global__ void sgc_reorder(const int* __restrict__ src, const int* __restrict__ dst,
                            const float* __restrict__ wt, int* __restrict__ cursor,
                            int2* __restrict__ csr, int E)
{
    int i = blockIdx.x * blockDim.x + threadIdx.x;
    if (i < E) {
        int d = dst[i];
        int pos = atomicAdd(&cursor[d], 1);
        csr[pos] = make_int2(src[i], __float_as_int(wt[i]));
    }
}

// ---------------------------------------------------------------------------
// Gather hop: B[dst] = sum_{e in CSR[dst]} w_e * A[src_e].  16 lanes/node,
// one float4/lane, unroll-2 with dual accumulators for memory-level parallelism.
// No atomics, no pre-zeroing.
// ---------------------------------------------------------------------------
__global__ __launch_bounds__(256) void sgc_gather_kernel(
    const float4* __restrict__ A, float4* __restrict__ B,
    const int* __restrict__ off, const int* __restrict__ deg,
    const int2* __restrict__ csr, int n_nodes)
{
    int node = blockIdx.x * 16 + (threadIdx.x >> 4);
    int lane = threadIdx.x & 15;
    if (node >= n_nodes) return;

    int e   = __ldg(off + node);
    int end = e + __ldg(deg + node);

    float4 acc0 = make_float4(0.f, 0.f, 0.f, 0.f);
    float4 acc1 = make_float4(0.f, 0.f, 0.f, 0.f);

    for (; e + 1 < end; e += 2) {
        int2 ew0 = __ldg(&csr[e]);
        int2 ew1 = __ldg(&csr[e + 1]);
        float4 a0 = __ldg(&A[(size_t)ew0.x * 16 + lane]);
        float4 a1 = __ldg(&A[(size_t)ew1.x * 16 + lane]);
        float w0 = __int_as_float(ew0.y);
        float w1 = __int_as_float(ew1.y);
        acc0.x += w0 * a0.x; acc0.y += w0 * a0.y;
        acc0.z += w0 * a0.z; acc0.w += w0 * a0.w;
        acc1.x += w1 * a1.x; acc1.y += w1 * a1.y;
        acc1.z += w1 * a1.z; acc1.w += w1 * a1.w;
    }
    if (e < end) {
        int2 ew = __ldg(&csr[e]);
        float4 a = __ldg(&A[(size_t)ew.x * 16 + lane]);
        float w = __int_as_float(ew.y);
        acc0.x += w * a.x; acc0.y += w * a.y;
        acc0.z += w * a.z; acc0.w += w * a.w;
    }
    acc0.x += acc1.x; acc0.y += acc1.y; acc0.z += acc1.z; acc0.w += acc1.w;
    B[(size_t)node * 16 + lane] = acc0;
}

// ---------------------------------------------------------------------------
// Launch
// ---------------------------------------------------------------------------
extern "C" void kernel_launch(void* const* d_in, const int* in_sizes, int n_in,
                              void* d_out, int out_size)
{
    const float* x   = (const float*)d_in[0];
    const float* W   = (const float*)d_in[1];
    const float* b   = (const float*)d_in[2];
    const int*   src = (const int*)  d_in[3];
    const int*   dst = (const int*)  d_in[4];
    const float* wt  = (const float*)d_in[5];

    const int N = in_sizes[0] / IN_F;
    const int E = in_sizes[3];
    float* out  = (float*)d_out;

    float *buf0, *buf1;
    int *deg, *off, *cursor, *bsum;
    int2 *csr;
    cudaGetSymbolAddress((void**)&buf0,   g_buf0);
    cudaGetSymbolAddress((void**)&buf1,   g_buf1);
    cudaGetSymbolAddress((void**)&deg,    g_deg);
    cudaGetSymbolAddress((void**)&off,    g_off);
    cudaGetSymbolAddress((void**)&cursor, g_cursor);
    cudaGetSymbolAddress((void**)&bsum,   g_bsum);
    cudaGetSymbolAddress((void**)&csr,    g_csr);

    const int NB = (N + 1023) / 1024;           // scan blocks (<=256)
    const int nThreadBlksN = (N + 255) / 256;
    const int nThreadBlksE = (E + 255) / 256;
    const int gemmBlks     = (N + TM - 1) / TM;
    const int gatherBlks   = (N + 15) / 16;

    // --- CSR build (once; reused by all 3 hops) ---
    sgc_zero_deg<<<nThreadBlksN, 256>>>(deg, N);
    sgc_hist<<<nThreadBlksE, 256>>>(dst, deg, E);
    sgc_scanA<<<NB, 256>>>(deg, off, bsum, N);
    sgc_scanB<<<1, 256>>>(bsum, NB);
    sgc_scanC<<<nThreadBlksN, 256>>>(off, cursor, bsum, N);
    sgc_reorder<<<nThreadBlksE, 256>>>(src, dst, wt, cursor, csr, E);

    // --- Projection: buf0 = x @ W.T + b ---
    sgc_gemm_kernel<<<gemmBlks, 256>>>(x, W, b, buf0, N);

    // --- 3 gather hops (no zeroing, no atomics) ---
    sgc_gather_kernel<<<gatherBlks, 256>>>((const float4*)buf0, (float4*)buf1,
                                           off, deg, csr, N);
    sgc_gather_kernel<<<gatherBlks, 256>>>((const float4*)buf1, (float4*)buf0,
                                           off, deg, csr, N);
    sgc_gather_kernel<<<gatherBlks, 256>>>((const float4*)buf0, (float4*)out,
                                           off, deg, csr, N);
}

// round 5
// speedup vs baseline: 1.5565x; 1.0157x over previous
#include <cuda_runtime.h>
#include <cuda_fp16.h>
#include <stdint.h>

#define IN_F   256
#define OUT_F  64
#define MAX_NODES 100000
#define MAX_EDGES 1600000

// ---------------------------------------------------------------------------
// Device-global scratch (allocation-free)
// ---------------------------------------------------------------------------
__device__ __half g_h0[(size_t)MAX_NODES * OUT_F];   // fp16 feature ping
__device__ __half g_h1[(size_t)MAX_NODES * OUT_F];   // fp16 feature pong
__device__ int   g_deg[MAX_NODES];
__device__ int   g_off[MAX_NODES];
__device__ int   g_cursor[MAX_NODES];
__device__ int   g_bsum[128];
__device__ int2  g_csr[MAX_EDGES];   // (src, weight bits), grouped by dst

// ---------------------------------------------------------------------------
// f32x2 packed-FMA helpers (Blackwell: only reachable via PTX)
// ---------------------------------------------------------------------------
__device__ __forceinline__ unsigned long long pack2(float lo, float hi) {
    unsigned long long r;
    asm("mov.b64 %0, {%1,%2};" : "=l"(r) : "f"(lo), "f"(hi));
    return r;
}
__device__ __forceinline__ void unpack2(unsigned long long v, float& lo, float& hi) {
    asm("mov.b64 {%0,%1}, %2;" : "=f"(lo), "=f"(hi) : "l"(v));
}
__device__ __forceinline__ unsigned long long fma2(unsigned long long a,
                                                   unsigned long long b,
                                                   unsigned long long c) {
    unsigned long long d;
    asm("fma.rn.f32x2 %0, %1, %2, %3;" : "=l"(d) : "l"(a), "l"(b), "l"(c));
    return d;
}

// ---------------------------------------------------------------------------
// GEMM: y[n,f] = sum_k x[n,k]*W[f,k] + b[f]   (fp32 math, fp16 output)
// 64-node x 64-feat x 32-k tiles; thread = 4 nodes x 4 feats (strided by 16);
// k-pair packed FFMA2, horizontal add at the end.
// ---------------------------------------------------------------------------
#define TM 64
#define TK 32
#define LD 34   // leading dim: 17 (odd) 8B-units -> conflict-free LDS.64

__global__ __launch_bounds__(256, 2) void sgc_gemm_kernel(
    const float* __restrict__ x, const float* __restrict__ W,
    const float* __restrict__ bias, __half* __restrict__ y, int n_nodes)
{
    __shared__ float As[TM][LD];
    __shared__ float Bs[OUT_F][LD];

    const int t  = threadIdx.x;
    const int tx = t & 15;     // feats: tx, tx+16, tx+32, tx+48
    const int ty = t >> 4;     // nodes: ty, ty+16, ty+32, ty+48
    const int node_base = blockIdx.x * TM;

    unsigned long long acc[4][4];
    #pragma unroll
    for (int j = 0; j < 4; j++) {
        unsigned long long binit = pack2(bias[tx + 16 * j], 0.0f);
        #pragma unroll
        for (int i = 0; i < 4; i++) acc[i][j] = binit;
    }

    for (int k0 = 0; k0 < IN_F; k0 += TK) {
        #pragma unroll
        for (int r = 0; r < 2; r++) {
            int idx = t + r * 256;
            int row = idx >> 3;
            int kq  = idx & 7;
            int gn  = node_base + row;
            float4 v = make_float4(0.f, 0.f, 0.f, 0.f);
            if (gn < n_nodes)
                v = *reinterpret_cast<const float4*>(x + (size_t)gn * IN_F + k0 + kq * 4);
            float2* p = reinterpret_cast<float2*>(&As[row][kq * 4]);
            p[0] = make_float2(v.x, v.y);
            p[1] = make_float2(v.z, v.w);
        }
        #pragma unroll
        for (int r = 0; r < 2; r++) {
            int idx = t + r * 256;
            int f   = idx >> 3;
            int kq  = idx & 7;
            float4 v = *reinterpret_cast<const float4*>(W + (size_t)f * IN_F + k0 + kq * 4);
            float2* p = reinterpret_cast<float2*>(&Bs[f][kq * 4]);
            p[0] = make_float2(v.x, v.y);
            p[1] = make_float2(v.z, v.w);
        }
        __syncthreads();

        #pragma unroll
        for (int k = 0; k < TK; k += 2) {
            unsigned long long a2[4], b2[4];
            #pragma unroll
            for (int i = 0; i < 4; i++)
                a2[i] = *reinterpret_cast<const unsigned long long*>(&As[ty + 16 * i][k]);
            #pragma unroll
            for (int j = 0; j < 4; j++)
                b2[j] = *reinterpret_cast<const unsigned long long*>(&Bs[tx + 16 * j][k]);
            #pragma unroll
            for (int i = 0; i < 4; i++)
                #pragma unroll
                for (int j = 0; j < 4; j++)
                    acc[i][j] = fma2(a2[i], b2[j], acc[i][j]);
        }
        __syncthreads();
    }

    #pragma unroll
    for (int i = 0; i < 4; i++) {
        int gn = node_base + ty + 16 * i;
        if (gn < n_nodes) {
            #pragma unroll
            for (int j = 0; j < 4; j++) {
                float lo, hi;
                unpack2(acc[i][j], lo, hi);
                y[(size_t)gn * OUT_F + tx + 16 * j] = __float2half(lo + hi);
            }
        }
    }
}

// ---------------------------------------------------------------------------
// CSR build: memset(deg) -> histogram -> scanA -> scanC(fused block-sum scan)
//            -> reorder
// ---------------------------------------------------------------------------
__global__ void sgc_hist(const int* __restrict__ dst, int* __restrict__ deg, int E)
{
    int i = blockIdx.x * blockDim.x + threadIdx.x;
    if (i < E) atomicAdd(&deg[dst[i]], 1);   // no return use -> REDG
}

__global__ void sgc_scanA(const int* __restrict__ deg, int* __restrict__ off,
                          int* __restrict__ bsum, int n)
{
    __shared__ int s[256];
    int t = threadIdx.x;
    int base = blockIdx.x * 1024 + t * 4;
    int v0 = (base + 0 < n) ? deg[base + 0] : 0;
    int v1 = (base + 1 < n) ? deg[base + 1] : 0;
    int v2 = (base + 2 < n) ? deg[base + 2] : 0;
    int v3 = (base + 3 < n) ? deg[base + 3] : 0;
    int tsum = v0 + v1 + v2 + v3;
    s[t] = tsum;
    __syncthreads();
    for (int o = 1; o < 256; o <<= 1) {
        int xv = (t >= o) ? s[t - o] : 0;
        __syncthreads();
        s[t] += xv;
        __syncthreads();
    }
    int excl = s[t] - tsum;
    if (t == 255) bsum[blockIdx.x] = s[255];
    if (base + 0 < n) off[base + 0] = excl;
    if (base + 1 < n) off[base + 1] = excl + v0;
    if (base + 2 < n) off[base + 2] = excl + v0 + v1;
    if (base + 3 < n) off[base + 3] = excl + v0 + v1 + v2;
}

// Fused: every block re-scans the (<=128) block sums in smem, then applies
// the exclusive block prefix to its 256 offsets. Kills the serial scanB launch.
__global__ void sgc_scanC(int* __restrict__ off, int* __restrict__ cursor,
                          const int* __restrict__ bsum, int n, int nb)
{
    __shared__ int s[128];
    int t = threadIdx.x;
    if (t < 128) s[t] = (t < nb) ? bsum[t] : 0;
    __syncthreads();
    #pragma unroll
    for (int o = 1; o < 128; o <<= 1) {
        int v = (t < 128 && t >= o) ? s[t - o] : 0;
        __syncthreads();
        if (t < 128) s[t] += v;
        __syncthreads();
    }
    int i = blockIdx.x * 256 + t;
    if (i < n) {
        int blk = i >> 10;
        int pref = (blk == 0) ? 0 : s[blk - 1];
        int v = off[i] + pref;
        off[i] = v;
        cursor[i] = v;
    }
}

__global__ void sgc_reorder(const int* __restrict__ src, const int* __restrict__ dst,
                            const float* __restrict__ wt, int* __restrict__ cursor,
                            int2* __restrict__ csr, int E)
{
    int i = blockIdx.x * blockDim.x + threadIdx.x;
    if (i < E) {
        int d = dst[i];
        int pos = atomicAdd(&cursor[d], 1);
        csr[pos] = make_int2(src[i], __float_as_int(wt[i]));
    }
}

// ---------------------------------------------------------------------------
// Gather hop (fp16 A, fp32 accumulate): B[dst] = sum w_e * A[src_e].
// 8 lanes/node, one uint4 (8 halves) per lane; unroll-2 dual accumulators.
// LAST=true writes fp32 to d_out, else writes fp16 ping-pong buffer.
// ---------------------------------------------------------------------------
__device__ __forceinline__ void acc8(float2* acc, uint4 r, float w)
{
    const __half2* h = reinterpret_cast<const __half2*>(&r);
    #pragma unroll
    for (int i = 0; i < 4; i++) {
        float2 f = __half22float2(h[i]);
        acc[i].x += w * f.x;
        acc[i].y += w * f.y;
    }
}

template <bool LAST>
__global__ __launch_bounds__(256) void sgc_gather_kernel(
    const uint4* __restrict__ A, __half* __restrict__ Bh, float* __restrict__ Bf,
    const int* __restrict__ off, const int* __restrict__ deg,
    const int2* __restrict__ csr, int n_nodes)
{
    int node = blockIdx.x * 32 + (threadIdx.x >> 3);
    int lane = threadIdx.x & 7;
    if (node >= n_nodes) return;

    int e   = __ldg(off + node);
    int end = e + __ldg(deg + node);

    float2 a0[4] = {{0.f,0.f},{0.f,0.f},{0.f,0.f},{0.f,0.f}};
    float2 a1[4] = {{0.f,0.f},{0.f,0.f},{0.f,0.f},{0.f,0.f}};

    for (; e + 1 < end; e += 2) {
        int2 ew0 = __ldg(&csr[e]);
        int2 ew1 = __ldg(&csr[e + 1]);
        uint4 r0 = __ldg(&A[ew0.x * 8 + lane]);
        uint4 r1 = __ldg(&A[ew1.x * 8 + lane]);
        acc8(a0, r0, __int_as_float(ew0.y));
        acc8(a1, r1, __int_as_float(ew1.y));
    }
    if (e < end) {
        int2 ew = __ldg(&csr[e]);
        uint4 r = __ldg(&A[ew.x * 8 + lane]);
        acc8(a0, r, __int_as_float(ew.y));
    }
    #pragma unroll
    for (int i = 0; i < 4; i++) {
        a0[i].x += a1[i].x;
        a0[i].y += a1[i].y;
    }

    if (LAST) {
        float* p = Bf + (size_t)node * OUT_F + lane * 8;
        *reinterpret_cast<float4*>(p)     = make_float4(a0[0].x, a0[0].y, a0[1].x, a0[1].y);
        *reinterpret_cast<float4*>(p + 4) = make_float4(a0[2].x, a0[2].y, a0[3].x, a0[3].y);
    } else {
        uint4 o;
        __half2 h0 = __floats2half2_rn(a0[0].x, a0[0].y);
        __half2 h1 = __floats2half2_rn(a0[1].x, a0[1].y);
        __half2 h2 = __floats2half2_rn(a0[2].x, a0[2].y);
        __half2 h3 = __floats2half2_rn(a0[3].x, a0[3].y);
        o.x = *reinterpret_cast<unsigned*>(&h0);
        o.y = *reinterpret_cast<unsigned*>(&h1);
        o.z = *reinterpret_cast<unsigned*>(&h2);
        o.w = *reinterpret_cast<unsigned*>(&h3);
        reinterpret_cast<uint4*>(Bh)[node * 8 + lane] = o;
    }
}

// ---------------------------------------------------------------------------
// Launch
// ---------------------------------------------------------------------------
extern "C" void kernel_launch(void* const* d_in, const int* in_sizes, int n_in,
                              void* d_out, int out_size)
{
    const float* x   = (const float*)d_in[0];
    const float* W   = (const float*)d_in[1];
    const float* b   = (const float*)d_in[2];
    const int*   src = (const int*)  d_in[3];
    const int*   dst = (const int*)  d_in[4];
    const float* wt  = (const float*)d_in[5];

    const int N = in_sizes[0] / IN_F;
    const int E = in_sizes[3];
    float* out  = (float*)d_out;

    __half *h0, *h1;
    int *deg, *off, *cursor, *bsum;
    int2 *csr;
    cudaGetSymbolAddress((void**)&h0,     g_h0);
    cudaGetSymbolAddress((void**)&h1,     g_h1);
    cudaGetSymbolAddress((void**)&deg,    g_deg);
    cudaGetSymbolAddress((void**)&off,    g_off);
    cudaGetSymbolAddress((void**)&cursor, g_cursor);
    cudaGetSymbolAddress((void**)&bsum,   g_bsum);
    cudaGetSymbolAddress((void**)&csr,    g_csr);

    const int NB          = (N + 1023) / 1024;     // scanA blocks (<=128)
    const int blksN256    = (N + 255) / 256;
    const int blksE256    = (E + 255) / 256;
    const int gemmBlks    = (N + TM - 1) / TM;
    const int gatherBlks  = (N + 31) / 32;

    // --- CSR build (reused by all 3 hops) ---
    cudaMemsetAsync(deg, 0, (size_t)N * sizeof(int));
    sgc_hist<<<blksE256, 256>>>(dst, deg, E);
    sgc_scanA<<<NB, 256>>>(deg, off, bsum, N);
    sgc_scanC<<<blksN256, 256>>>(off, cursor, bsum, N, NB);
    sgc_reorder<<<blksE256, 256>>>(src, dst, wt, cursor, csr, E);

    // --- Projection: h0 = fp16(x @ W.T + b) ---
    sgc_gemm_kernel<<<gemmBlks, 256>>>(x, W, b, h0, N);

    // --- 3 gather hops (fp16 reads, fp32 math; last writes fp32 out) ---
    sgc_gather_kernel<false><<<gatherBlks, 256>>>((const uint4*)h0, h1, nullptr,
                                                  off, deg, csr, N);
    sgc_gather_kernel<false><<<gatherBlks, 256>>>((const uint4*)h1, h0, nullptr,
                                                  off, deg, csr, N);
    sgc_gather_kernel<true><<<gatherBlks, 256>>>((const uint4*)h0, nullptr, out,
                                                 off, deg, csr, N);
}

// round 6
// speedup vs baseline: 1.5714x; 1.0096x over previous
#include <cuda_runtime.h>
#include <cuda_fp16.h>
#include <stdint.h>

#define IN_F   256
#define OUT_F  64
#define MAX_NODES 100000
#define MAX_EDGES 1600000

// ---------------------------------------------------------------------------
// Device-global scratch (allocation-free)
// ---------------------------------------------------------------------------
__device__ __half g_h0[(size_t)MAX_NODES * OUT_F];   // fp16 feature ping
__device__ __half g_h1[(size_t)MAX_NODES * OUT_F];   // fp16 feature pong
__device__ int   g_deg[MAX_NODES];
__device__ int   g_off[MAX_NODES];
__device__ int   g_rank[MAX_EDGES];
__device__ int   g_bsum[128];
__device__ int2  g_csr[MAX_EDGES];   // (src, weight bits), grouped by dst

// ---------------------------------------------------------------------------
// f32x2 packed-FMA helpers (Blackwell: only reachable via PTX)
// ---------------------------------------------------------------------------
__device__ __forceinline__ unsigned long long pack2(float lo, float hi) {
    unsigned long long r;
    asm("mov.b64 %0, {%1,%2};" : "=l"(r) : "f"(lo), "f"(hi));
    return r;
}
__device__ __forceinline__ void unpack2(unsigned long long v, float& lo, float& hi) {
    asm("mov.b64 {%0,%1}, %2;" : "=f"(lo), "=f"(hi) : "l"(v));
}
__device__ __forceinline__ unsigned long long fma2(unsigned long long a,
                                                   unsigned long long b,
                                                   unsigned long long c) {
    unsigned long long d;
    asm("fma.rn.f32x2 %0, %1, %2, %3;" : "=l"(d) : "l"(a), "l"(b), "l"(c));
    return d;
}

// ---------------------------------------------------------------------------
// GEMM: y[n,f] = sum_k x[n,k]*W[f,k] + b[f]   (fp32 math, fp16 output)
// ---------------------------------------------------------------------------
#define TM 64
#define TK 32
#define LD 34   // 17 (odd) 8B-units -> conflict-free LDS.64

__global__ __launch_bounds__(256, 2) void sgc_gemm_kernel(
    const float* __restrict__ x, const float* __restrict__ W,
    const float* __restrict__ bias, __half* __restrict__ y, int n_nodes)
{
    __shared__ float As[TM][LD];
    __shared__ float Bs[OUT_F][LD];

    const int t  = threadIdx.x;
    const int tx = t & 15;
    const int ty = t >> 4;
    const int node_base = blockIdx.x * TM;

    unsigned long long acc[4][4];
    #pragma unroll
    for (int j = 0; j < 4; j++) {
        unsigned long long binit = pack2(bias[tx + 16 * j], 0.0f);
        #pragma unroll
        for (int i = 0; i < 4; i++) acc[i][j] = binit;
    }

    for (int k0 = 0; k0 < IN_F; k0 += TK) {
        #pragma unroll
        for (int r = 0; r < 2; r++) {
            int idx = t + r * 256;
            int row = idx >> 3;
            int kq  = idx & 7;
            int gn  = node_base + row;
            float4 v = make_float4(0.f, 0.f, 0.f, 0.f);
            if (gn < n_nodes)
                v = *reinterpret_cast<const float4*>(x + (size_t)gn * IN_F + k0 + kq * 4);
            float2* p = reinterpret_cast<float2*>(&As[row][kq * 4]);
            p[0] = make_float2(v.x, v.y);
            p[1] = make_float2(v.z, v.w);
        }
        #pragma unroll
        for (int r = 0; r < 2; r++) {
            int idx = t + r * 256;
            int f   = idx >> 3;
            int kq  = idx & 7;
            float4 v = *reinterpret_cast<const float4*>(W + (size_t)f * IN_F + k0 + kq * 4);
            float2* p = reinterpret_cast<float2*>(&Bs[f][kq * 4]);
            p[0] = make_float2(v.x, v.y);
            p[1] = make_float2(v.z, v.w);
        }
        __syncthreads();

        #pragma unroll
        for (int k = 0; k < TK; k += 2) {
            unsigned long long a2[4], b2[4];
            #pragma unroll
            for (int i = 0; i < 4; i++)
                a2[i] = *reinterpret_cast<const unsigned long long*>(&As[ty + 16 * i][k]);
            #pragma unroll
            for (int j = 0; j < 4; j++)
                b2[j] = *reinterpret_cast<const unsigned long long*>(&Bs[tx + 16 * j][k]);
            #pragma unroll
            for (int i = 0; i < 4; i++)
                #pragma unroll
                for (int j = 0; j < 4; j++)
                    acc[i][j] = fma2(a2[i], b2[j], acc[i][j]);
        }
        __syncthreads();
    }

    #pragma unroll
    for (int i = 0; i < 4; i++) {
        int gn = node_base + ty + 16 * i;
        if (gn < n_nodes) {
            #pragma unroll
            for (int j = 0; j < 4; j++) {
                float lo, hi;
                unpack2(acc[i][j], lo, hi);
                y[(size_t)gn * OUT_F + tx + 16 * j] = __float2half(lo + hi);
            }
        }
    }
}

// ---------------------------------------------------------------------------
// CSR build: memset(deg) -> hist(+rank) -> scanA -> scanC -> reorder(no atomic)
// ---------------------------------------------------------------------------
__global__ void sgc_hist(const int* __restrict__ dst, int* __restrict__ deg,
                         int* __restrict__ rank, int E)
{
    int i = blockIdx.x * blockDim.x + threadIdx.x;
    if (i < E) rank[i] = atomicAdd(&deg[dst[i]], 1);   // rank within dst bucket
}

__global__ void sgc_scanA(const int* __restrict__ deg, int* __restrict__ off,
                          int* __restrict__ bsum, int n)
{
    __shared__ int s[256];
    int t = threadIdx.x;
    int base = blockIdx.x * 1024 + t * 4;
    int v0 = (base + 0 < n) ? deg[base + 0] : 0;
    int v1 = (base + 1 < n) ? deg[base + 1] : 0;
    int v2 = (base + 2 < n) ? deg[base + 2] : 0;
    int v3 = (base + 3 < n) ? deg[base + 3] : 0;
    int tsum = v0 + v1 + v2 + v3;
    s[t] = tsum;
    __syncthreads();
    for (int o = 1; o < 256; o <<= 1) {
        int xv = (t >= o) ? s[t - o] : 0;
        __syncthreads();
        s[t] += xv;
        __syncthreads();
    }
    int excl = s[t] - tsum;
    if (t == 255) bsum[blockIdx.x] = s[255];
    if (base + 0 < n) off[base + 0] = excl;
    if (base + 1 < n) off[base + 1] = excl + v0;
    if (base + 2 < n) off[base + 2] = excl + v0 + v1;
    if (base + 3 < n) off[base + 3] = excl + v0 + v1 + v2;
}

// Every block re-scans the (<=128) block sums in smem and applies the
// exclusive block prefix to its 256 offsets (no serial scanB launch).
__global__ void sgc_scanC(int* __restrict__ off, const int* __restrict__ bsum,
                          int n, int nb)
{
    __shared__ int s[128];
    int t = threadIdx.x;
    if (t < 128) s[t] = (t < nb) ? bsum[t] : 0;
    __syncthreads();
    #pragma unroll
    for (int o = 1; o < 128; o <<= 1) {
        int v = (t < 128 && t >= o) ? s[t - o] : 0;
        __syncthreads();
        if (t < 128) s[t] += v;
        __syncthreads();
    }
    int i = blockIdx.x * 256 + t;
    if (i < n) {
        int blk = i >> 10;
        int pref = (blk == 0) ? 0 : s[blk - 1];
        off[i] += pref;
    }
}

// Atomic-free reorder: position = off[dst] + rank (rank captured in hist).
__global__ void sgc_reorder(const int* __restrict__ src, const int* __restrict__ dst,
                            const float* __restrict__ wt,
                            const int* __restrict__ off, const int* __restrict__ rank,
                            int2* __restrict__ csr, int E)
{
    int i = blockIdx.x * blockDim.x + threadIdx.x;
    if (i < E) {
        int pos = __ldg(off + dst[i]) + rank[i];
        csr[pos] = make_int2(src[i], __float_as_int(wt[i]));
    }
}

// ---------------------------------------------------------------------------
// Gather hop (fp16 A, fp32 accumulate): B[dst] = sum w_e * A[src_e].
// 8 lanes/node, one uint4 (8 halves) per lane; unroll-4 (4 independent csr
// loads, then 4 independent feature loads) for MLP=4; dual accumulator sets.
// ---------------------------------------------------------------------------
__device__ __forceinline__ void acc8(float2* acc, uint4 r, float w)
{
    const __half2* h = reinterpret_cast<const __half2*>(&r);
    #pragma unroll
    for (int i = 0; i < 4; i++) {
        float2 f = __half22float2(h[i]);
        acc[i].x += w * f.x;
        acc[i].y += w * f.y;
    }
}

template <bool LAST>
__global__ __launch_bounds__(256) void sgc_gather_kernel(
    const uint4* __restrict__ A, __half* __restrict__ Bh, float* __restrict__ Bf,
    const int* __restrict__ off, const int* __restrict__ deg,
    const int2* __restrict__ csr, int n_nodes)
{
    int node = blockIdx.x * 32 + (threadIdx.x >> 3);
    int lane = threadIdx.x & 7;
    if (node >= n_nodes) return;

    int e   = __ldg(off + node);
    int end = e + __ldg(deg + node);

    float2 a0[4] = {{0.f,0.f},{0.f,0.f},{0.f,0.f},{0.f,0.f}};
    float2 a1[4] = {{0.f,0.f},{0.f,0.f},{0.f,0.f},{0.f,0.f}};

    for (; e + 4 <= end; e += 4) {
        int2 ew0 = __ldg(&csr[e]);
        int2 ew1 = __ldg(&csr[e + 1]);
        int2 ew2 = __ldg(&csr[e + 2]);
        int2 ew3 = __ldg(&csr[e + 3]);
        uint4 r0 = __ldg(&A[ew0.x * 8 + lane]);
        uint4 r1 = __ldg(&A[ew1.x * 8 + lane]);
        uint4 r2 = __ldg(&A[ew2.x * 8 + lane]);
        uint4 r3 = __ldg(&A[ew3.x * 8 + lane]);
        acc8(a0, r0, __int_as_float(ew0.y));
        acc8(a1, r1, __int_as_float(ew1.y));
        acc8(a0, r2, __int_as_float(ew2.y));
        acc8(a1, r3, __int_as_float(ew3.y));
    }
    for (; e < end; e++) {
        int2 ew = __ldg(&csr[e]);
        uint4 r = __ldg(&A[ew.x * 8 + lane]);
        acc8(a0, r, __int_as_float(ew.y));
    }
    #pragma unroll
    for (int i = 0; i < 4; i++) {
        a0[i].x += a1[i].x;
        a0[i].y += a1[i].y;
    }

    if (LAST) {
        float* p = Bf + (size_t)node * OUT_F + lane * 8;
        *reinterpret_cast<float4*>(p)     = make_float4(a0[0].x, a0[0].y, a0[1].x, a0[1].y);
        *reinterpret_cast<float4*>(p + 4) = make_float4(a0[2].x, a0[2].y, a0[3].x, a0[3].y);
    } else {
        uint4 o;
        __half2 h0 = __floats2half2_rn(a0[0].x, a0[0].y);
        __half2 h1 = __floats2half2_rn(a0[1].x, a0[1].y);
        __half2 h2 = __floats2half2_rn(a0[2].x, a0[2].y);
        __half2 h3 = __floats2half2_rn(a0[3].x, a0[3].y);
        o.x = *reinterpret_cast<unsigned*>(&h0);
        o.y = *reinterpret_cast<unsigned*>(&h1);
        o.z = *reinterpret_cast<unsigned*>(&h2);
        o.w = *reinterpret_cast<unsigned*>(&h3);
        reinterpret_cast<uint4*>(Bh)[node * 8 + lane] = o;
    }
}

// ---------------------------------------------------------------------------
// Launch
// ---------------------------------------------------------------------------
extern "C" void kernel_launch(void* const* d_in, const int* in_sizes, int n_in,
                              void* d_out, int out_size)
{
    const float* x   = (const float*)d_in[0];
    const float* W   = (const float*)d_in[1];
    const float* b   = (const float*)d_in[2];
    const int*   src = (const int*)  d_in[3];
    const int*   dst = (const int*)  d_in[4];
    const float* wt  = (const float*)d_in[5];

    const int N = in_sizes[0] / IN_F;
    const int E = in_sizes[3];
    float* out  = (float*)d_out;

    __half *h0, *h1;
    int *deg, *off, *rank, *bsum;
    int2 *csr;
    cudaGetSymbolAddress((void**)&h0,   g_h0);
    cudaGetSymbolAddress((void**)&h1,   g_h1);
    cudaGetSymbolAddress((void**)&deg,  g_deg);
    cudaGetSymbolAddress((void**)&off,  g_off);
    cudaGetSymbolAddress((void**)&rank, g_rank);
    cudaGetSymbolAddress((void**)&bsum, g_bsum);
    cudaGetSymbolAddress((void**)&csr,  g_csr);

    const int NB         = (N + 1023) / 1024;   // scanA blocks (<=128)
    const int blksN256   = (N + 255) / 256;
    const int blksE256   = (E + 255) / 256;
    const int gemmBlks   = (N + TM - 1) / TM;
    const int gatherBlks = (N + 31) / 32;

    // --- CSR build (reused by all 3 hops) ---
    cudaMemsetAsync(deg, 0, (size_t)N * sizeof(int));
    sgc_hist<<<blksE256, 256>>>(dst, deg, rank, E);
    sgc_scanA<<<NB, 256>>>(deg, off, bsum, N);
    sgc_scanC<<<blksN256, 256>>>(off, bsum, N, NB);
    sgc_reorder<<<blksE256, 256>>>(src, dst, wt, off, rank, csr, E);

    // --- Projection: h0 = fp16(x @ W.T + b) ---
    sgc_gemm_kernel<<<gemmBlks, 256>>>(x, W, b, h0, N);

    // --- 3 gather hops (fp16 reads, fp32 math; last writes fp32 out) ---
    sgc_gather_kernel<false><<<gatherBlks, 256>>>((const uint4*)h0, h1, nullptr,
                                                  off, deg, csr, N);
    sgc_gather_kernel<false><<<gatherBlks, 256>>>((const uint4*)h1, h0, nullptr,
                                                  off, deg, csr, N);
    sgc_gather_kernel<true><<<gatherBlks, 256>>>((const uint4*)h0, nullptr, out,
                                                 off, deg, csr, N);
}

// round 7
// speedup vs baseline: 1.5888x; 1.0111x over previous
#include <cuda_runtime.h>
#include <cuda_fp16.h>
#include <mma.h>
#include <stdint.h>

#define IN_F   256
#define OUT_F  64
#define MAX_NODES 100000
#define MAX_EDGES 1600000

// ---------------------------------------------------------------------------
// Device-global scratch (allocation-free)
// ---------------------------------------------------------------------------
__device__ __half g_h0[(size_t)MAX_NODES * OUT_F];   // fp16 feature ping
__device__ __half g_h1[(size_t)MAX_NODES * OUT_F];   // fp16 feature pong
__device__ __half g_Wh[OUT_F * IN_F];                // fp16 weights
__device__ int   g_deg[MAX_NODES];
__device__ int   g_off[MAX_NODES];
__device__ int   g_rank[MAX_EDGES];
__device__ int   g_bsum[128];
__device__ int2  g_csr[MAX_EDGES];   // (src, weight bits), grouped by dst

// ---------------------------------------------------------------------------
// W fp32 -> fp16 (once)
// ---------------------------------------------------------------------------
__global__ void sgc_cvtW(const float* __restrict__ W, __half* __restrict__ Wh, int n)
{
    int i = blockIdx.x * blockDim.x + threadIdx.x;
    if (i < n) Wh[i] = __float2half(W[i]);
}

// ---------------------------------------------------------------------------
// Tensor-core GEMM: y[n,f] = fp16( sum_k x[n,k]*W[f,k] + b[f] )
// Block: 128 nodes x 64 feats, 8 warps (16-node strip each), wmma m16n16k16.
// A: fp32 x streamed -> fp16 smem tiles.  B: fp16 W in smem ([f][k] row-major
// == (k,f) col-major, ldm=256).  fp32 accumulate, fp32 bias, fp16 store.
// ---------------------------------------------------------------------------
#define GM 128          // nodes per block
#define ALD 24          // As leading dim (halves), multiple of 8

union GemmSmem {
    struct {
        __half Ws[OUT_F * IN_F];   // 32768 B
        __half As[GM * ALD];       //  6144 B
    } in;
    float stage[GM * OUT_F];       // 32768 B
};

__global__ __launch_bounds__(256) void sgc_gemm_kernel(
    const float* __restrict__ x, const __half* __restrict__ Wh,
    const float* __restrict__ bias, __half* __restrict__ y, int n_nodes)
{
    using namespace nvcuda;
    __shared__ GemmSmem sm;

    const int t    = threadIdx.x;
    const int warp = t >> 5;
    const int node_base = blockIdx.x * GM;

    // Stage W into smem: 32KB = 2048 uint4
    {
        const uint4* src = reinterpret_cast<const uint4*>(Wh);
        uint4* dst = reinterpret_cast<uint4*>(sm.in.Ws);
        #pragma unroll
        for (int r = 0; r < 8; r++) dst[t + r * 256] = src[t + r * 256];
    }

    wmma::fragment<wmma::accumulator, 16, 16, 16, float> c[4];
    #pragma unroll
    for (int j = 0; j < 4; j++) wmma::fill_fragment(c[j], 0.0f);

    for (int k0 = 0; k0 < IN_F; k0 += 16) {
        __syncthreads();
        // Load A tile: 128 rows x 16 k (fp32 -> fp16). 512 float4, 2/thread.
        #pragma unroll
        for (int r = 0; r < 2; r++) {
            int idx = t + r * 256;
            int row = idx >> 2;
            int q   = idx & 3;
            int gn  = node_base + row;
            float4 v = make_float4(0.f, 0.f, 0.f, 0.f);
            if (gn < n_nodes)
                v = *reinterpret_cast<const float4*>(x + (size_t)gn * IN_F + k0 + q * 4);
            __half2* p = reinterpret_cast<__half2*>(&sm.in.As[row * ALD + q * 4]);
            p[0] = __floats2half2_rn(v.x, v.y);
            p[1] = __floats2half2_rn(v.z, v.w);
        }
        __syncthreads();

        wmma::fragment<wmma::matrix_a, 16, 16, 16, __half, wmma::row_major> a;
        wmma::load_matrix_sync(a, &sm.in.As[warp * 16 * ALD], ALD);
        #pragma unroll
        for (int j = 0; j < 4; j++) {
            wmma::fragment<wmma::matrix_b, 16, 16, 16, __half, wmma::col_major> bf;
            wmma::load_matrix_sync(bf, &sm.in.Ws[(j * 16) * IN_F + k0], IN_F);
            wmma::mma_sync(c[j], a, bf, c[j]);
        }
    }

    __syncthreads();   // done reading Ws/As; stage aliases them
    #pragma unroll
    for (int j = 0; j < 4; j++)
        wmma::store_matrix_sync(&sm.stage[(warp * 16) * OUT_F + j * 16], c[j],
                                OUT_F, wmma::mem_row_major);
    __syncthreads();

    // Epilogue: +bias (fp32), convert, fp16 store. Thread = half a row (32 f).
    {
        int row  = t >> 1;
        int part = (t & 1) * 32;
        int gn   = node_base + row;
        if (gn < n_nodes) {
            uint4 o[1];
            __half* oh = reinterpret_cast<__half*>(o);
            #pragma unroll
            for (int seg = 0; seg < 4; seg++) {
                #pragma unroll
                for (int cix = 0; cix < 8; cix++) {
                    int f = part + seg * 8 + cix;
                    oh[cix] = __float2half(sm.stage[row * OUT_F + f] + bias[f]);
                }
                reinterpret_cast<uint4*>(y + (size_t)gn * OUT_F + part)[seg] = o[0];
            }
        }
    }
}

// ---------------------------------------------------------------------------
// CSR build: memset(deg) -> hist(+rank) -> scanA -> scanC -> reorder(no atomic)
// ---------------------------------------------------------------------------
__global__ void sgc_hist(const int* __restrict__ dst, int* __restrict__ deg,
                         int* __restrict__ rank, int E)
{
    int i = blockIdx.x * blockDim.x + threadIdx.x;
    if (i < E) rank[i] = atomicAdd(&deg[dst[i]], 1);
}

__global__ void sgc_scanA(const int* __restrict__ deg, int* __restrict__ off,
                          int* __restrict__ bsum, int n)
{
    __shared__ int s[256];
    int t = threadIdx.x;
    int base = blockIdx.x * 1024 + t * 4;
    int v0 = (base + 0 < n) ? deg[base + 0] : 0;
    int v1 = (base + 1 < n) ? deg[base + 1] : 0;
    int v2 = (base + 2 < n) ? deg[base + 2] : 0;
    int v3 = (base + 3 < n) ? deg[base + 3] : 0;
    int tsum = v0 + v1 + v2 + v3;
    s[t] = tsum;
    __syncthreads();
    for (int o = 1; o < 256; o <<= 1) {
        int xv = (t >= o) ? s[t - o] : 0;
        __syncthreads();
        s[t] += xv;
        __syncthreads();
    }
    int excl = s[t] - tsum;
    if (t == 255) bsum[blockIdx.x] = s[255];
    if (base + 0 < n) off[base + 0] = excl;
    if (base + 1 < n) off[base + 1] = excl + v0;
    if (base + 2 < n) off[base + 2] = excl + v0 + v1;
    if (base + 3 < n) off[base + 3] = excl + v0 + v1 + v2;
}

__global__ void sgc_scanC(int* __restrict__ off, const int* __restrict__ bsum,
                          int n, int nb)
{
    __shared__ int s[128];
    int t = threadIdx.x;
    if (t < 128) s[t] = (t < nb) ? bsum[t] : 0;
    __syncthreads();
    #pragma unroll
    for (int o = 1; o < 128; o <<= 1) {
        int v = (t < 128 && t >= o) ? s[t - o] : 0;
        __syncthreads();
        if (t < 128) s[t] += v;
        __syncthreads();
    }
    int i = blockIdx.x * 256 + t;
    if (i < n) {
        int blk = i >> 10;
        int pref = (blk == 0) ? 0 : s[blk - 1];
        off[i] += pref;
    }
}

// Atomic-free reorder, 2 independent edge chains per thread (MLP=2).
__global__ void sgc_reorder(const int* __restrict__ src, const int* __restrict__ dst,
                            const float* __restrict__ wt,
                            const int* __restrict__ off, const int* __restrict__ rank,
                            int2* __restrict__ csr, int E)
{
    int i = (blockIdx.x * blockDim.x + threadIdx.x) * 2;
    if (i + 1 < E) {
        int d0 = dst[i],  d1 = dst[i + 1];
        int r0 = rank[i], r1 = rank[i + 1];
        int o0 = __ldg(off + d0);
        int o1 = __ldg(off + d1);
        int2 e0 = make_int2(src[i],     __float_as_int(wt[i]));
        int2 e1 = make_int2(src[i + 1], __float_as_int(wt[i + 1]));
        csr[o0 + r0] = e0;
        csr[o1 + r1] = e1;
    } else if (i < E) {
        csr[__ldg(off + dst[i]) + rank[i]] = make_int2(src[i], __float_as_int(wt[i]));
    }
}

// ---------------------------------------------------------------------------
// Gather hop: warp-per-node (zero intra-warp divergence; iterations = deg).
// Lane owns 2 feats (half2 = 4B load, coalesced 128B/edge). Unroll-4, dual acc.
// ---------------------------------------------------------------------------
template <bool LAST>
__global__ __launch_bounds__(256) void sgc_gather_kernel(
    const unsigned* __restrict__ A, __half* __restrict__ Bh, float* __restrict__ Bf,
    const int* __restrict__ off, const int* __restrict__ deg,
    const int2* __restrict__ csr, int n_nodes)
{
    int node = blockIdx.x * 8 + (threadIdx.x >> 5);
    int lane = threadIdx.x & 31;
    if (node >= n_nodes) return;

    int e   = __ldg(off + node);
    int end = e + __ldg(deg + node);

    float2 a0 = make_float2(0.f, 0.f);
    float2 a1 = make_float2(0.f, 0.f);

    for (; e + 4 <= end; e += 4) {
        int2 ew0 = __ldg(&csr[e]);
        int2 ew1 = __ldg(&csr[e + 1]);
        int2 ew2 = __ldg(&csr[e + 2]);
        int2 ew3 = __ldg(&csr[e + 3]);
        unsigned r0 = __ldg(&A[ew0.x * 32 + lane]);
        unsigned r1 = __ldg(&A[ew1.x * 32 + lane]);
        unsigned r2 = __ldg(&A[ew2.x * 32 + lane]);
        unsigned r3 = __ldg(&A[ew3.x * 32 + lane]);
        float2 f0 = __half22float2(*reinterpret_cast<__half2*>(&r0));
        float2 f1 = __half22float2(*reinterpret_cast<__half2*>(&r1));
        float2 f2 = __half22float2(*reinterpret_cast<__half2*>(&r2));
        float2 f3 = __half22float2(*reinterpret_cast<__half2*>(&r3));
        float w0 = __int_as_float(ew0.y), w1 = __int_as_float(ew1.y);
        float w2 = __int_as_float(ew2.y), w3 = __int_as_float(ew3.y);
        a0.x += w0 * f0.x; a0.y += w0 * f0.y;
        a1.x += w1 * f1.x; a1.y += w1 * f1.y;
        a0.x += w2 * f2.x; a0.y += w2 * f2.y;
        a1.x += w3 * f3.x; a1.y += w3 * f3.y;
    }
    for (; e < end; e++) {
        int2 ew = __ldg(&csr[e]);
        unsigned r = __ldg(&A[ew.x * 32 + lane]);
        float2 f = __half22float2(*reinterpret_cast<__half2*>(&r));
        float w = __int_as_float(ew.y);
        a0.x += w * f.x; a0.y += w * f.y;
    }
    a0.x += a1.x; a0.y += a1.y;

    if (LAST) {
        reinterpret_cast<float2*>(Bf)[(size_t)node * 32 + lane] = a0;
    } else {
        __half2 h = __floats2half2_rn(a0.x, a0.y);
        reinterpret_cast<__half2*>(Bh)[(size_t)node * 32 + lane] = h;
    }
}

// ---------------------------------------------------------------------------
// Launch
// ---------------------------------------------------------------------------
extern "C" void kernel_launch(void* const* d_in, const int* in_sizes, int n_in,
                              void* d_out, int out_size)
{
    const float* x   = (const float*)d_in[0];
    const float* W   = (const float*)d_in[1];
    const float* b   = (const float*)d_in[2];
    const int*   src = (const int*)  d_in[3];
    const int*   dst = (const int*)  d_in[4];
    const float* wt  = (const float*)d_in[5];

    const int N = in_sizes[0] / IN_F;
    const int E = in_sizes[3];
    float* out  = (float*)d_out;

    __half *h0, *h1, *Wh;
    int *deg, *off, *rank, *bsum;
    int2 *csr;
    cudaGetSymbolAddress((void**)&h0,   g_h0);
    cudaGetSymbolAddress((void**)&h1,   g_h1);
    cudaGetSymbolAddress((void**)&Wh,   g_Wh);
    cudaGetSymbolAddress((void**)&deg,  g_deg);
    cudaGetSymbolAddress((void**)&off,  g_off);
    cudaGetSymbolAddress((void**)&rank, g_rank);
    cudaGetSymbolAddress((void**)&bsum, g_bsum);
    cudaGetSymbolAddress((void**)&csr,  g_csr);

    const int NB         = (N + 1023) / 1024;
    const int blksN256   = (N + 255) / 256;
    const int blksE256   = (E + 255) / 256;
    const int blksE512   = (E + 511) / 512;
    const int gemmBlks   = (N + GM - 1) / GM;
    const int gatherBlks = (N + 7) / 8;

    // --- CSR build (reused by all 3 hops) ---
    cudaMemsetAsync(deg, 0, (size_t)N * sizeof(int));
    sgc_hist<<<blksE256, 256>>>(dst, deg, rank, E);
    sgc_scanA<<<NB, 256>>>(deg, off, bsum, N);
    sgc_scanC<<<blksN256, 256>>>(off, bsum, N, NB);
    sgc_reorder<<<blksE512, 256>>>(src, dst, wt, off, rank, csr, E);

    // --- Projection (tensor cores): h0 = fp16(x @ W.T + b) ---
    sgc_cvtW<<<(OUT_F * IN_F + 255) / 256, 256>>>(W, Wh, OUT_F * IN_F);
    sgc_gemm_kernel<<<gemmBlks, 256>>>(x, Wh, b, h0, N);

    // --- 3 gather hops (fp16 reads, fp32 math; last writes fp32 out) ---
    sgc_gather_kernel<false><<<gatherBlks, 256>>>((const unsigned*)h0, h1, nullptr,
                                                  off, deg, csr, N);
    sgc_gather_kernel<false><<<gatherBlks, 256>>>((const unsigned*)h1, h0, nullptr,
                                                  off, deg, csr, N);
    sgc_gather_kernel<true><<<gatherBlks, 256>>>((const unsigned*)h0, nullptr, out,
                                                 off, deg, csr, N);
}

// round 8
// speedup vs baseline: 1.9199x; 1.2084x over previous
#include <cuda_runtime.h>
#include <cuda_fp16.h>
#include <mma.h>
#include <stdint.h>

#define IN_F   256
#define OUT_F  64
#define MAX_NODES 100000
#define MAX_EDGES 1600000

// ---------------------------------------------------------------------------
// Device-global scratch (allocation-free)
// ---------------------------------------------------------------------------
__device__ __half g_h0[(size_t)MAX_NODES * OUT_F];   // fp16 feature ping
__device__ __half g_h1[(size_t)MAX_NODES * OUT_F];   // fp16 feature pong
__device__ int   g_deg[MAX_NODES];
__device__ int   g_off[MAX_NODES];
__device__ int   g_rank[MAX_EDGES];
__device__ int   g_bsum[128];
__device__ int2  g_csr[MAX_EDGES];   // (src, weight bits), grouped by dst

// ---------------------------------------------------------------------------
// Tensor-core GEMM: y[n,f] = fp16( sum_k x[n,k]*W[f,k] + b[f] )
// W staged fp32->fp16 into smem inside the kernel (no cvtW pass).
// ---------------------------------------------------------------------------
#define GM 128          // nodes per block
#define ALD 24          // As leading dim (halves), multiple of 8

union GemmSmem {
    struct {
        __half Ws[OUT_F * IN_F];   // 32768 B
        __half As[GM * ALD];       //  6144 B
    } in;
    float stage[GM * OUT_F];       // 32768 B
};

__global__ __launch_bounds__(256) void sgc_gemm_kernel(
    const float* __restrict__ x, const float* __restrict__ W,
    const float* __restrict__ bias, __half* __restrict__ y, int n_nodes)
{
    using namespace nvcuda;
    __shared__ GemmSmem sm;

    const int t    = threadIdx.x;
    const int warp = t >> 5;
    const int node_base = blockIdx.x * GM;

    // Stage W (fp32 global) -> fp16 smem: 4096 float4 loads, 16/thread.
    {
        const float4* src = reinterpret_cast<const float4*>(W);
        __half2* dst = reinterpret_cast<__half2*>(sm.in.Ws);
        #pragma unroll
        for (int r = 0; r < 16; r++) {
            int idx4 = t + r * 256;
            float4 v = src[idx4];
            dst[idx4 * 2 + 0] = __floats2half2_rn(v.x, v.y);
            dst[idx4 * 2 + 1] = __floats2half2_rn(v.z, v.w);
        }
    }

    wmma::fragment<wmma::accumulator, 16, 16, 16, float> c[4];
    #pragma unroll
    for (int j = 0; j < 4; j++) wmma::fill_fragment(c[j], 0.0f);

    for (int k0 = 0; k0 < IN_F; k0 += 16) {
        __syncthreads();
        #pragma unroll
        for (int r = 0; r < 2; r++) {
            int idx = t + r * 256;
            int row = idx >> 2;
            int q   = idx & 3;
            int gn  = node_base + row;
            float4 v = make_float4(0.f, 0.f, 0.f, 0.f);
            if (gn < n_nodes)
                v = *reinterpret_cast<const float4*>(x + (size_t)gn * IN_F + k0 + q * 4);
            __half2* p = reinterpret_cast<__half2*>(&sm.in.As[row * ALD + q * 4]);
            p[0] = __floats2half2_rn(v.x, v.y);
            p[1] = __floats2half2_rn(v.z, v.w);
        }
        __syncthreads();

        wmma::fragment<wmma::matrix_a, 16, 16, 16, __half, wmma::row_major> a;
        wmma::load_matrix_sync(a, &sm.in.As[warp * 16 * ALD], ALD);
        #pragma unroll
        for (int j = 0; j < 4; j++) {
            wmma::fragment<wmma::matrix_b, 16, 16, 16, __half, wmma::col_major> bf;
            wmma::load_matrix_sync(bf, &sm.in.Ws[(j * 16) * IN_F + k0], IN_F);
            wmma::mma_sync(c[j], a, bf, c[j]);
        }
    }

    __syncthreads();
    #pragma unroll
    for (int j = 0; j < 4; j++)
        wmma::store_matrix_sync(&sm.stage[(warp * 16) * OUT_F + j * 16], c[j],
                                OUT_F, wmma::mem_row_major);
    __syncthreads();

    {
        int row  = t >> 1;
        int part = (t & 1) * 32;
        int gn   = node_base + row;
        if (gn < n_nodes) {
            uint4 o[1];
            __half* oh = reinterpret_cast<__half*>(o);
            #pragma unroll
            for (int seg = 0; seg < 4; seg++) {
                #pragma unroll
                for (int cix = 0; cix < 8; cix++) {
                    int f = part + seg * 8 + cix;
                    oh[cix] = __float2half(sm.stage[row * OUT_F + f] + bias[f]);
                }
                reinterpret_cast<uint4*>(y + (size_t)gn * OUT_F + part)[seg] = o[0];
            }
        }
    }
}

// ---------------------------------------------------------------------------
// CSR build
// ---------------------------------------------------------------------------
__global__ void sgc_hist(const int* __restrict__ dst, int* __restrict__ deg,
                         int* __restrict__ rank, int E)
{
    int i = blockIdx.x * blockDim.x + threadIdx.x;
    if (i < E) rank[i] = atomicAdd(&deg[dst[i]], 1);
}

__global__ void sgc_scanA(const int* __restrict__ deg, int* __restrict__ off,
                          int* __restrict__ bsum, int n)
{
    __shared__ int s[256];
    int t = threadIdx.x;
    int base = blockIdx.x * 1024 + t * 4;
    int v0 = (base + 0 < n) ? deg[base + 0] : 0;
    int v1 = (base + 1 < n) ? deg[base + 1] : 0;
    int v2 = (base + 2 < n) ? deg[base + 2] : 0;
    int v3 = (base + 3 < n) ? deg[base + 3] : 0;
    int tsum = v0 + v1 + v2 + v3;
    s[t] = tsum;
    __syncthreads();
    for (int o = 1; o < 256; o <<= 1) {
        int xv = (t >= o) ? s[t - o] : 0;
        __syncthreads();
        s[t] += xv;
        __syncthreads();
    }
    int excl = s[t] - tsum;
    if (t == 255) bsum[blockIdx.x] = s[255];
    if (base + 0 < n) off[base + 0] = excl;
    if (base + 1 < n) off[base + 1] = excl + v0;
    if (base + 2 < n) off[base + 2] = excl + v0 + v1;
    if (base + 3 < n) off[base + 3] = excl + v0 + v1 + v2;
}

__global__ void sgc_scanC(int* __restrict__ off, const int* __restrict__ bsum,
                          int n, int nb)
{
    __shared__ int s[128];
    int t = threadIdx.x;
    if (t < 128) s[t] = (t < nb) ? bsum[t] : 0;
    __syncthreads();
    #pragma unroll
    for (int o = 1; o < 128; o <<= 1) {
        int v = (t < 128 && t >= o) ? s[t - o] : 0;
        __syncthreads();
        if (t < 128) s[t] += v;
        __syncthreads();
    }
    int i = blockIdx.x * 256 + t;
    if (i < n) {
        int blk = i >> 10;
        int pref = (blk == 0) ? 0 : s[blk - 1];
        off[i] += pref;
    }
}

// Atomic-free reorder, 4 independent grid-strided chains per thread (MLP=4).
__global__ void sgc_reorder(const int* __restrict__ src, const int* __restrict__ dst,
                            const float* __restrict__ wt,
                            const int* __restrict__ off, const int* __restrict__ rank,
                            int2* __restrict__ csr, int E, int T)
{
    int i0 = blockIdx.x * blockDim.x + threadIdx.x;
    int i1 = i0 + T, i2 = i0 + 2 * T, i3 = i0 + 3 * T;

    int d0 = (i0 < E) ? dst[i0] : 0;
    int d1 = (i1 < E) ? dst[i1] : 0;
    int d2 = (i2 < E) ? dst[i2] : 0;
    int d3 = (i3 < E) ? dst[i3] : 0;
    int r0 = (i0 < E) ? rank[i0] : 0;
    int r1 = (i1 < E) ? rank[i1] : 0;
    int r2 = (i2 < E) ? rank[i2] : 0;
    int r3 = (i3 < E) ? rank[i3] : 0;
    int o0 = __ldg(off + d0);
    int o1 = __ldg(off + d1);
    int o2 = __ldg(off + d2);
    int o3 = __ldg(off + d3);
    if (i0 < E) csr[o0 + r0] = make_int2(src[i0], __float_as_int(wt[i0]));
    if (i1 < E) csr[o1 + r1] = make_int2(src[i1], __float_as_int(wt[i1]));
    if (i2 < E) csr[o2 + r2] = make_int2(src[i2], __float_as_int(wt[i2]));
    if (i3 < E) csr[o3 + r3] = make_int2(src[i3], __float_as_int(wt[i3]));
}

// ---------------------------------------------------------------------------
// Gather hop: 16 lanes/node (2 nodes per warp), uint2 = 4 fp16 feats per lane,
// unroll-4 (4 independent csr + 4 independent feature loads per node).
// ---------------------------------------------------------------------------
__device__ __forceinline__ void accP(float2& ax, float2& ay, uint2 r, float w)
{
    float2 f0 = __half22float2(*reinterpret_cast<__half2*>(&r.x));
    float2 f1 = __half22float2(*reinterpret_cast<__half2*>(&r.y));
    ax.x += w * f0.x; ax.y += w * f0.y;
    ay.x += w * f1.x; ay.y += w * f1.y;
}

template <bool LAST>
__global__ __launch_bounds__(512) void sgc_gather_kernel(
    const uint2* __restrict__ A, __half* __restrict__ Bh, float* __restrict__ Bf,
    const int* __restrict__ off, const int* __restrict__ deg,
    const int2* __restrict__ csr, int n_nodes)
{
    int warp = threadIdx.x >> 5;
    int lane = threadIdx.x & 31;
    int slot = lane >> 4;          // 0 or 1: which node in warp
    int fl   = lane & 15;          // feature-lane: feats [fl*4, fl*4+4)
    int node = blockIdx.x * 32 + warp * 2 + slot;
    if (node >= n_nodes) return;

    int e   = __ldg(off + node);
    int end = e + __ldg(deg + node);

    float2 ax0 = {0.f,0.f}, ay0 = {0.f,0.f};
    float2 ax1 = {0.f,0.f}, ay1 = {0.f,0.f};

    for (; e + 4 <= end; e += 4) {
        int2 ew0 = __ldg(&csr[e]);
        int2 ew1 = __ldg(&csr[e + 1]);
        int2 ew2 = __ldg(&csr[e + 2]);
        int2 ew3 = __ldg(&csr[e + 3]);
        uint2 r0 = __ldg(&A[ew0.x * 16 + fl]);
        uint2 r1 = __ldg(&A[ew1.x * 16 + fl]);
        uint2 r2 = __ldg(&A[ew2.x * 16 + fl]);
        uint2 r3 = __ldg(&A[ew3.x * 16 + fl]);
        accP(ax0, ay0, r0, __int_as_float(ew0.y));
        accP(ax1, ay1, r1, __int_as_float(ew1.y));
        accP(ax0, ay0, r2, __int_as_float(ew2.y));
        accP(ax1, ay1, r3, __int_as_float(ew3.y));
    }
    for (; e < end; e++) {
        int2 ew = __ldg(&csr[e]);
        uint2 r = __ldg(&A[ew.x * 16 + fl]);
        accP(ax0, ay0, r, __int_as_float(ew.y));
    }
    ax0.x += ax1.x; ax0.y += ax1.y;
    ay0.x += ay1.x; ay0.y += ay1.y;

    if (LAST) {
        reinterpret_cast<float4*>(Bf)[(size_t)node * 16 + fl] =
            make_float4(ax0.x, ax0.y, ay0.x, ay0.y);
    } else {
        __half2 h0 = __floats2half2_rn(ax0.x, ax0.y);
        __half2 h1 = __floats2half2_rn(ay0.x, ay0.y);
        uint2 o;
        o.x = *reinterpret_cast<unsigned*>(&h0);
        o.y = *reinterpret_cast<unsigned*>(&h1);
        reinterpret_cast<uint2*>(Bh)[(size_t)node * 16 + fl] = o;
    }
}

// ---------------------------------------------------------------------------
// Launch: GEMM forked onto a side stream, joined before hop1.
// ---------------------------------------------------------------------------
extern "C" void kernel_launch(void* const* d_in, const int* in_sizes, int n_in,
                              void* d_out, int out_size)
{
    const float* x   = (const float*)d_in[0];
    const float* W   = (const float*)d_in[1];
    const float* b   = (const float*)d_in[2];
    const int*   src = (const int*)  d_in[3];
    const int*   dst = (const int*)  d_in[4];
    const float* wt  = (const float*)d_in[5];

    const int N = in_sizes[0] / IN_F;
    const int E = in_sizes[3];
    float* out  = (float*)d_out;

    __half *h0, *h1;
    int *deg, *off, *rank, *bsum;
    int2 *csr;
    cudaGetSymbolAddress((void**)&h0,   g_h0);
    cudaGetSymbolAddress((void**)&h1,   g_h1);
    cudaGetSymbolAddress((void**)&deg,  g_deg);
    cudaGetSymbolAddress((void**)&off,  g_off);
    cudaGetSymbolAddress((void**)&rank, g_rank);
    cudaGetSymbolAddress((void**)&bsum, g_bsum);
    cudaGetSymbolAddress((void**)&csr,  g_csr);

    // One-time resource setup (no device memory; identical work every call).
    static cudaStream_t s2 = nullptr;
    static cudaEvent_t evFork = nullptr, evJoin = nullptr;
    if (s2 == nullptr) {
        cudaStreamCreateWithFlags(&s2, cudaStreamNonBlocking);
        cudaEventCreateWithFlags(&evFork, cudaEventDisableTiming);
        cudaEventCreateWithFlags(&evJoin, cudaEventDisableTiming);
    }

    const int NB         = (N + 1023) / 1024;
    const int blksN256   = (N + 255) / 256;
    const int blksE256   = (E + 255) / 256;
    const int gemmBlks   = (N + GM - 1) / GM;
    const int gatherBlks = (N + 31) / 32;
    const int reoT       = (E + 3) / 4;            // threads covering E/4
    const int reoBlks    = (reoT + 255) / 256;

    // --- Fork: GEMM on side stream (independent of CSR build) ---
    cudaEventRecord(evFork, 0);
    cudaStreamWaitEvent(s2, evFork, 0);
    sgc_gemm_kernel<<<gemmBlks, 256, 0, s2>>>(x, W, b, h0, N);
    cudaEventRecord(evJoin, s2);

    // --- CSR build on main stream ---
    cudaMemsetAsync(deg, 0, (size_t)N * sizeof(int));
    sgc_hist<<<blksE256, 256>>>(dst, deg, rank, E);
    sgc_scanA<<<NB, 256>>>(deg, off, bsum, N);
    sgc_scanC<<<blksN256, 256>>>(off, bsum, N, NB);
    sgc_reorder<<<reoBlks, 256>>>(src, dst, wt, off, rank, csr, E, reoBlks * 256);

    // --- Join, then 3 gather hops ---
    cudaStreamWaitEvent(0, evJoin, 0);
    sgc_gather_kernel<false><<<gatherBlks, 512>>>((const uint2*)h0, h1, nullptr,
                                                  off, deg, csr, N);
    sgc_gather_kernel<false><<<gatherBlks, 512>>>((const uint2*)h1, h0, nullptr,
                                                  off, deg, csr, N);
    sgc_gather_kernel<true><<<gatherBlks, 512>>>((const uint2*)h0, nullptr, out,
                                                 off, deg, csr, N);
}